// round 15
// baseline (speedup 1.0000x reference)
#include <cuda_runtime.h>
#include <cuda_bf16.h>

#define NLOC 256
#define NNEI 96
#define NG 96

typedef unsigned long long u64;

__device__ __forceinline__ u64 pack2(float lo, float hi){
    u64 r; asm("mov.b64 %0, {%1,%2};" : "=l"(r) : "f"(lo), "f"(hi)); return r;
}
__device__ __forceinline__ void unpack2(u64 v, float& lo, float& hi){
    asm("mov.b64 {%0,%1}, %2;" : "=f"(lo), "=f"(hi) : "l"(v));
}
// packed fp32x2 FMA (sm_100+): 2 full-precision fp32 FMAs per instruction
__device__ __forceinline__ u64 ffma2(u64 a, u64 b, u64 c){
    u64 d; asm("fma.rn.f32x2 %0, %1, %2, %3;" : "=l"(d) : "l"(a), "l"(b), "l"(c)); return d;
}
// accurate-enough tanh: 1 - 2/(exp(2x)+1) via ex2.approx + rcp.approx (~1e-7 err)
__device__ __forceinline__ float fast_tanh(float x){
    float e; asm("ex2.approx.f32 %0, %1;" : "=f"(e) : "f"(x * 2.88539008177792681f));
    float r; asm("rcp.approx.f32 %0, %1;" : "=f"(r) : "f"(e + 1.0f));
    return fmaf(-2.0f, r, 1.0f);
}

__global__ __launch_bounds__(192, 2)
void descrpt_se_t_kernel(const int*   __restrict__ nlist,
                         const float* __restrict__ coord,
                         const int*   __restrict__ atype,
                         const float* __restrict__ meanv,
                         const float* __restrict__ stdv,
                         const float* __restrict__ W1, const float* __restrict__ b1,
                         const float* __restrict__ W2, const float* __restrict__ b2,
                         const float* __restrict__ W3, const float* __restrict__ b3,
                         float* __restrict__ out)
{
    __shared__ __align__(16) float rrs[NNEI][4];
    __shared__ __align__(16) float h1s[64][24];
    __shared__ __align__(16) float h2s[64][48];
    __shared__ float xsraw[64];
    __shared__ float xsw[64];
    __shared__ float w1s[24], b1s[24];
    __shared__ float resbuf[NG];

    const int i   = blockIdx.x;
    const int tid = threadIdx.x;
    const int m    = tid % 96;       // output channel this thread owns
    const int half = tid / 96;       // element parity in phase C

    // ---- env matrix -> rr rows (only cols 1..3 are ever used downstream) ----
    if (tid < NNEI){
        int n  = tid;
        int nl = nlist[i*NNEI + n];
        bool mask = nl >= 0;
        int idx = mask ? nl : 0;
        float dx = coord[idx*3+0] - coord[i*3+0];
        float dy = coord[idx*3+1] - coord[i*3+1];
        float dz = coord[idx*3+2] - coord[i*3+2];
        float d2  = dx*dx + dy*dy + dz*dz;
        float len = sqrtf(d2) + (mask ? 0.f : 1.f);
        float inv2 = 1.f / (len*len);
        float sw;
        if (len <= 0.5f)      sw = 1.f;
        else if (len >= 6.f)  sw = 0.f;
        else {
            float uu = (len - 0.5f) * (1.f/5.5f);
            float pp = fmaf(fmaf(-6.f, uu, 15.f), uu, -10.f);
            sw = fmaf(uu*uu*uu, pp, 1.f);
        }
        if (!mask) sw = 0.f;
        int t  = atype[i];
        int mb = (t*NNEI + n)*4;
        rrs[n][0] = (dx*inv2*sw - meanv[mb+1]) / stdv[mb+1];
        rrs[n][1] = (dy*inv2*sw - meanv[mb+2]) / stdv[mb+2];
        rrs[n][2] = (dz*inv2*sw - meanv[mb+3]) / stdv[mb+3];
        rrs[n][3] = 0.f;
    }

    const int c2  = (m >= 48) ? (m - 48) : m;   // m % 48 (also == tid % 48)
    float tot = 0.f;

    #pragma unroll 1
    for (int p = 0; p < 3; ++p){
        int n, js, ks; bool tri; float scale; int E;
        if (p == 0)      { n=32; js=0;  ks=0;  tri=true;  scale=1.f/1024.f; E=528;  }
        else if (p == 1) { n=64; js=0;  ks=32; tri=false; scale=1.f/2048.f; E=2048; }
        else             { n=64; js=32; ks=32; tri=true;  scale=1.f/4096.f; E=2080; }
        const int ntiles = (E + 63) >> 6;

        // per-pair weight columns into registers (packed over K for f32x2)
        u64 w2p[12]; u64 w3p[24];
        const float* W2p = W2 + p*24*48;
        const float* W3p = W3 + p*48*96;
        #pragma unroll
        for (int q = 0; q < 12; ++q)
            w2p[q] = pack2(W2p[(2*q)*48 + c2], W2p[(2*q+1)*48 + c2]);
        #pragma unroll
        for (int q = 0; q < 24; ++q)
            w3p[q] = pack2(W3p[(2*q)*96 + m], W3p[(2*q+1)*96 + m]);
        float b2r = b2[p*48 + c2];
        float b3r = b3[p*96 + m];
        if (tid < 24){ w1s[tid] = W1[p*24 + tid]; b1s[tid] = b1[p*24 + tid]; }

        #pragma unroll 1
        for (int tile = 0; tile < ntiles; ++tile){
            const int e0 = tile << 6;
            __syncthreads();   // previous consumers done; w1s/rrs visible

            // ---- map 64 elements -> (j,k), compute env scalar x ----
            if (tid < 64){
                int el = e0 + tid;
                float sc = scale;
                int j, k; float wf = 1.f;
                if (tri){
                    int ec = el;
                    if (ec >= E){ ec = E-1; sc = 0.f; }   // padded slot
                    float nn = (float)n;
                    float disc = fmaf(-8.f, (float)ec, (2.f*nn+1.f)*(2.f*nn+1.f));
                    j = (int)(((2.f*nn+1.f) - sqrtf(disc)) * 0.5f);
                    if (j < 0) j = 0;
                    if (j > n-1) j = n-1;
                    int off = j*n - (j*(j-1))/2;
                    while (off > ec){ --j; off = j*n - (j*(j-1))/2; }
                    while (j < n-1){
                        int off2 = (j+1)*n - ((j+1)*j)/2;
                        if (off2 <= ec){ j = j+1; off = off2; } else break;
                    }
                    k = j + (ec - off);
                    if (k != j) wf = 2.f;   // symmetric block: count (j,k)+(k,j)
                } else {
                    j = el >> 6;
                    k = el & 63;
                }
                int jj = js + j, kk = ks + k;
                float x = rrs[jj][0]*rrs[kk][0] + rrs[jj][1]*rrs[kk][1] + rrs[jj][2]*rrs[kk][2];
                xsraw[tid] = x;
                xsw[tid]   = x * wf * sc;   // final-contraction weight folded in
            }
            __syncthreads();

            // ---- phase A: h1 = tanh(x*W1 + b1)  (64x24) ----
            #pragma unroll
            for (int it = 0; it < 8; ++it){
                int idx = it*192 + tid;
                int e = idx / 24;
                int c = idx - e*24;
                float x = xsraw[e];
                h1s[e][c] = fast_tanh(fmaf(x, w1s[c], b1s[c]));
            }
            __syncthreads();

            // ---- phase B: h2 = tanh(h1@W2 + b2) + h1[c%24]  (64x48) ----
            {
                int esub = tid / 48;              // 0..3
                int cb   = tid - esub*48;         // == c2
                int cskip = (cb >= 24) ? cb-24 : cb;
                #pragma unroll 2
                for (int it = 0; it < 16; ++it){
                    int e = 4*it + esub;
                    u64 accA = pack2(b2r, 0.f);
                    u64 accB = pack2(0.f, 0.f);
                    #pragma unroll
                    for (int q = 0; q < 6; ++q){
                        float4 v = *(const float4*)&h1s[e][4*q];
                        accA = ffma2(pack2(v.x, v.y), w2p[2*q],   accA);
                        accB = ffma2(pack2(v.z, v.w), w2p[2*q+1], accB);
                    }
                    float a0,a1,bb0,bb1; unpack2(accA,a0,a1); unpack2(accB,bb0,bb1);
                    float t = fast_tanh((a0+a1)+(bb0+bb1));
                    h2s[e][cb] = t + h1s[e][cskip];
                }
            }
            __syncthreads();

            // ---- phase C: res[m] += x * (tanh(h2@W3col + b3) + h2[m%48]) ----
            #pragma unroll 2
            for (int it = 0; it < 32; ++it){
                int e = 2*it + half;
                u64 accA = pack2(b3r, 0.f);
                u64 accB = pack2(0.f, 0.f);
                #pragma unroll
                for (int q = 0; q < 12; ++q){
                    float4 v = *(const float4*)&h2s[e][4*q];
                    accA = ffma2(pack2(v.x, v.y), w3p[2*q],   accA);
                    accB = ffma2(pack2(v.z, v.w), w3p[2*q+1], accB);
                }
                float a0,a1,bb0,bb1; unpack2(accA,a0,a1); unpack2(accB,bb0,bb1);
                float g = fast_tanh((a0+a1)+(bb0+bb1)) + h2s[e][c2];
                tot = fmaf(xsw[e], g, tot);
            }
        }
    }

    // combine the two element-halves and write out
    if (half == 1) resbuf[m] = tot;
    __syncthreads();
    if (half == 0) out[i*NG + m] = tot + resbuf[m];
}

extern "C" void kernel_launch(void* const* d_in, const int* in_sizes, int n_in,
                              void* d_out, int out_size)
{
    const int*   nlist = (const int*)  d_in[0];
    const float* coord = (const float*)d_in[1];
    const int*   atype = (const int*)  d_in[2];
    const float* meanv = (const float*)d_in[3];
    const float* stdv  = (const float*)d_in[4];
    const float* W1    = (const float*)d_in[5];
    const float* b1    = (const float*)d_in[6];
    const float* W2    = (const float*)d_in[7];
    const float* b2    = (const float*)d_in[8];
    const float* W3    = (const float*)d_in[9];
    const float* b3    = (const float*)d_in[10];

    descrpt_se_t_kernel<<<NLOC, 192>>>(nlist, coord, atype, meanv, stdv,
                                       W1, b1, W2, b2, W3, b3, (float*)d_out);
}

// round 16
// speedup vs baseline: 1.2113x; 1.2113x over previous
#include <cuda_runtime.h>
#include <cuda_bf16.h>

#define NLOC 256
#define NNEI 96
#define NG 96
#define NPART 4
#define NOUT (NLOC*NG)          // 24576
#define NELEM 4736              // 576 + 2048 + 2112 (padded per-pair element blocks)

typedef unsigned long long u64;

// partial results, one slice per part-CTA (no atomics -> deterministic)
__device__ float g_part[NPART * NOUT];

__device__ __forceinline__ u64 pack2(float lo, float hi){
    u64 r; asm("mov.b64 %0, {%1,%2};" : "=l"(r) : "f"(lo), "f"(hi)); return r;
}
__device__ __forceinline__ void unpack2(u64 v, float& lo, float& hi){
    asm("mov.b64 {%0,%1}, %2;" : "=f"(lo), "=f"(hi) : "l"(v));
}
__device__ __forceinline__ u64 ffma2(u64 a, u64 b, u64 c){
    u64 d; asm("fma.rn.f32x2 %0, %1, %2, %3;" : "=l"(d) : "l"(a), "l"(b), "l"(c)); return d;
}
__device__ __forceinline__ u64 fadd2(u64 a, u64 b){
    u64 d; asm("add.rn.f32x2 %0, %1, %2;" : "=l"(d) : "l"(a), "l"(b)); return d;
}
// tanh = 1 - 2/(exp(2x)+1) via ex2.approx + rcp.approx (~1e-7 rel err)
__device__ __forceinline__ float fast_tanh(float x){
    float e; asm("ex2.approx.f32 %0, %1;" : "=f"(e) : "f"(x * 2.88539008177792681f));
    float r; asm("rcp.approx.f32 %0, %1;" : "=f"(r) : "f"(e + 1.0f));
    return fmaf(-2.0f, r, 1.0f);
}

struct __align__(16) Smem {
    float xsraw[NELEM];       // raw env scalar x per (pair,element)
    float xsw[NELEM];         // x * symmetry_weight * scale (0 on padded slots)
    float h1s[64][24];
    float h2s[64][48];
    float rrs[96][4];
    float red[2][4][48];      // [channel-half][quarter][m2]
};

__global__ __launch_bounds__(192, 2)
void descrpt_se_t_main(const int*   __restrict__ nlist,
                       const float* __restrict__ coord,
                       const int*   __restrict__ atype,
                       const float* __restrict__ meanv,
                       const float* __restrict__ stdv,
                       const float* __restrict__ W1, const float* __restrict__ b1,
                       const float* __restrict__ W2, const float* __restrict__ b2,
                       const float* __restrict__ W3, const float* __restrict__ b3)
{
    extern __shared__ __align__(16) char smraw[];
    Smem* sm = (Smem*)smraw;

    const int bid  = blockIdx.x;
    const int i    = bid >> 2;      // atom
    const int part = bid & 3;       // tile-stride slice
    const int tid  = threadIdx.x;

    // ---- env rows (only diff components 1..3 are used downstream) ----
    if (tid < NNEI){
        int n  = tid;
        int nl = nlist[i*NNEI + n];
        bool mask = nl >= 0;
        int idx = mask ? nl : 0;
        float dx = coord[idx*3+0] - coord[i*3+0];
        float dy = coord[idx*3+1] - coord[i*3+1];
        float dz = coord[idx*3+2] - coord[i*3+2];
        float d2  = dx*dx + dy*dy + dz*dz;
        float len = sqrtf(d2) + (mask ? 0.f : 1.f);
        float inv2 = 1.f / (len*len);
        float sw;
        if (len <= 0.5f)      sw = 1.f;
        else if (len >= 6.f)  sw = 0.f;
        else {
            float uu = (len - 0.5f) * (1.f/5.5f);
            float pp = fmaf(fmaf(-6.f, uu, 15.f), uu, -10.f);
            sw = fmaf(uu*uu*uu, pp, 1.f);
        }
        if (!mask) sw = 0.f;
        int t  = atype[i];
        int mb = (t*NNEI + n)*4;
        sm->rrs[n][0] = (dx*inv2*sw - meanv[mb+1]) / stdv[mb+1];
        sm->rrs[n][1] = (dy*inv2*sw - meanv[mb+2]) / stdv[mb+2];
        sm->rrs[n][2] = (dz*inv2*sw - meanv[mb+3]) / stdv[mb+3];
        sm->rrs[n][3] = 0.f;
    }
    // zero xs (covers padded slots)
    for (int e = tid; e < NELEM; e += 192){ sm->xsraw[e] = 0.f; sm->xsw[e] = 0.f; }
    __syncthreads();

    // ---- precompute ALL env scalars once (kills the per-tile serial search) ----
    // pair 1 (0,1): dense 32x64 at base 576, scale 1/2048
    for (int el = tid; el < 2048; el += 192){
        int j = el >> 6, k = el & 63;
        float4 a = *(const float4*)sm->rrs[j];
        float4 b = *(const float4*)sm->rrs[32 + k];
        float x = a.x*b.x + a.y*b.y + a.z*b.z;
        sm->xsraw[576 + el] = x;
        sm->xsw[576 + el]   = x * (1.f/2048.f);
    }
    // triangular pairs: p0 (n=32, base 0, 1/1024), p2 (n=64, base 2624, 1/4096)
    if (tid < 96){
        int row = tid;
        int j, n, base; float sc; int roff;
        if (row < 32){ j = row;      n = 32; base = 0;    sc = 1.f/1024.f; }
        else         { j = row - 32; n = 64; base = 2624; sc = 1.f/4096.f; }
        roff = (row < 32) ? 0 : 32;
        int off = base + j*n - (j*(j-1))/2 - j;   // entry for k sits at off + k
        float4 a = *(const float4*)sm->rrs[roff + j];
        for (int k = j; k < n; ++k){
            float4 b = *(const float4*)sm->rrs[roff + k];
            float x = a.x*b.x + a.y*b.y + a.z*b.z;
            sm->xsraw[off + k] = x;
            sm->xsw[off + k]   = x * sc * ((k == j) ? 1.f : 2.f);
        }
    }
    __syncthreads();

    // thread roles
    const int cA      = tid % 24;   // phase-A channel
    const int eA0     = tid / 24;   // phase-A element base (0..7)
    const int m2      = tid % 48;   // phase-B channel / phase-C channel pair (m2, m2+48)
    const int esub    = tid / 48;   // phase-B element offset (0..3)
    const int quarter = tid / 48;   // phase-C element offset (0..3)
    const int cskip   = (m2 >= 24) ? m2 - 24 : m2;

    float tot0 = 0.f, tot1 = 0.f;

    #pragma unroll 1
    for (int p = 0; p < 3; ++p){
        int ntl, pb;
        if (p == 0)      { ntl = 9;  pb = 0;    }
        else if (p == 1) { ntl = 32; pb = 576;  }
        else             { ntl = 33; pb = 2624; }

        // per-pair weights -> registers (packed over K for f32x2)
        u64 w2p[12], w3a[24], w3b[24];
        const float* W2p = W2 + p*24*48;
        const float* W3p = W3 + p*48*96;
        #pragma unroll
        for (int q = 0; q < 12; ++q)
            w2p[q] = pack2(W2p[(2*q)*48 + m2], W2p[(2*q+1)*48 + m2]);
        #pragma unroll
        for (int q = 0; q < 24; ++q){
            w3a[q] = pack2(W3p[(2*q)*96 + m2],      W3p[(2*q+1)*96 + m2]);
            w3b[q] = pack2(W3p[(2*q)*96 + m2 + 48], W3p[(2*q+1)*96 + m2 + 48]);
        }
        const float b2r  = b2[p*48 + m2];
        const float b3r0 = b3[p*96 + m2];
        const float b3r1 = b3[p*96 + m2 + 48];
        const float w1c  = W1[p*24 + cA];
        const float b1c  = b1[p*24 + cA];

        // ---- software-pipelined tiles: [A(t+1) || C(t)] share a barrier region ----
        int t = part;                 // every part has >=2 tiles for every pair (ntl>=9)
        {   // A(first)
            const int e0 = pb + (t << 6);
            #pragma unroll
            for (int it = 0; it < 8; ++it){
                int e = eA0 + 8*it;
                float x = sm->xsraw[e0 + e];
                sm->h1s[e][cA] = fast_tanh(fmaf(x, w1c, b1c));
            }
        }
        __syncthreads();

        #pragma unroll 1
        for (;;){
            // ---- phase B: h2 = tanh(h1@W2 + b2) + h1[c%24] ----
            #pragma unroll 2
            for (int it = 0; it < 16; ++it){
                int e = 4*it + esub;
                const ulonglong2* row = (const ulonglong2*)sm->h1s[e];
                u64 accA = pack2(b2r, 0.f);
                u64 accB = 0ULL;
                #pragma unroll
                for (int q = 0; q < 6; ++q){
                    ulonglong2 v = row[q];
                    accA = ffma2(v.x, w2p[2*q],   accA);
                    accB = ffma2(v.y, w2p[2*q+1], accB);
                }
                float lo, hi; unpack2(fadd2(accA, accB), lo, hi);
                sm->h2s[e][m2] = fast_tanh(lo + hi) + sm->h1s[e][cskip];
            }
            __syncthreads();

            const int e0c = pb + (t << 6);
            const int tn  = t + 4;

            // ---- phase A for next tile (overlaps with C in this region) ----
            if (tn < ntl){
                const int e0n = pb + (tn << 6);
                #pragma unroll
                for (int it = 0; it < 8; ++it){
                    int e = eA0 + 8*it;
                    float x = sm->xsraw[e0n + e];
                    sm->h1s[e][cA] = fast_tanh(fmaf(x, w1c, b1c));
                }
            }

            // ---- phase C: two channels per thread, h2 row shared across both ----
            #pragma unroll 2
            for (int itc = 0; itc < 16; ++itc){
                int e = 4*itc + quarter;
                const ulonglong2* row = (const ulonglong2*)sm->h2s[e];
                u64 a0A = pack2(b3r0, 0.f), a0B = 0ULL;
                u64 a1A = pack2(b3r1, 0.f), a1B = 0ULL;
                #pragma unroll
                for (int q = 0; q < 12; ++q){
                    ulonglong2 v = row[q];
                    a0A = ffma2(v.x, w3a[2*q],   a0A);
                    a0B = ffma2(v.y, w3a[2*q+1], a0B);
                    a1A = ffma2(v.x, w3b[2*q],   a1A);
                    a1B = ffma2(v.y, w3b[2*q+1], a1B);
                }
                float xw   = sm->xsw[e0c + e];
                float skip = sm->h2s[e][m2];
                float l0, h0; unpack2(fadd2(a0A, a0B), l0, h0);
                float l1, h1; unpack2(fadd2(a1A, a1B), l1, h1);
                float g0 = fast_tanh(l0 + h0) + skip;
                float g1 = fast_tanh(l1 + h1) + skip;
                tot0 = fmaf(xw, g0, tot0);
                tot1 = fmaf(xw, g1, tot1);
            }
            __syncthreads();

            if (tn >= ntl) break;
            t = tn;
        }
    }

    // ---- combine the 4 element-quarters, write this part's slice ----
    sm->red[0][quarter][m2] = tot0;
    sm->red[1][quarter][m2] = tot1;
    __syncthreads();
    if (tid < 96){
        int c = tid / 48, mm = tid % 48;
        float s = sm->red[c][0][mm] + sm->red[c][1][mm]
                + sm->red[c][2][mm] + sm->red[c][3][mm];
        g_part[part*NOUT + i*NG + c*48 + mm] = s;
    }
}

__global__ void descrpt_reduce(float* __restrict__ out)
{
    int idx = blockIdx.x * 256 + threadIdx.x;   // 96*256 = 24576 = NOUT
    out[idx] = g_part[idx]
             + g_part[idx + NOUT]
             + g_part[idx + 2*NOUT]
             + g_part[idx + 3*NOUT];
}

extern "C" void kernel_launch(void* const* d_in, const int* in_sizes, int n_in,
                              void* d_out, int out_size)
{
    const int*   nlist = (const int*)  d_in[0];
    const float* coord = (const float*)d_in[1];
    const int*   atype = (const int*)  d_in[2];
    const float* meanv = (const float*)d_in[3];
    const float* stdv  = (const float*)d_in[4];
    const float* W1    = (const float*)d_in[5];
    const float* b1    = (const float*)d_in[6];
    const float* W2    = (const float*)d_in[7];
    const float* b2    = (const float*)d_in[8];
    const float* W3    = (const float*)d_in[9];
    const float* b3    = (const float*)d_in[10];

    cudaFuncSetAttribute(descrpt_se_t_main,
                         cudaFuncAttributeMaxDynamicSharedMemorySize,
                         (int)sizeof(Smem));

    descrpt_se_t_main<<<NLOC * NPART, 192, sizeof(Smem)>>>(
        nlist, coord, atype, meanv, stdv, W1, b1, W2, b2, W3, b3);
    descrpt_reduce<<<NG, 256>>>((float*)d_out);
}

// round 17
// speedup vs baseline: 1.2115x; 1.0002x over previous
#include <cuda_runtime.h>
#include <cuda_bf16.h>

#define NLOC 256
#define NNEI 96
#define NG 96
#define NPART 4
#define NOUT (NLOC*NG)          // 24576
#define NELEM 4736              // 576 + 2048 + 2112 (padded per-pair element blocks)

typedef unsigned long long u64;

// partial results, one slice per part-CTA (no atomics -> deterministic)
__device__ float g_part[NPART * NOUT];

__device__ __forceinline__ u64 pack2(float lo, float hi){
    u64 r; asm("mov.b64 %0, {%1,%2};" : "=l"(r) : "f"(lo), "f"(hi)); return r;
}
__device__ __forceinline__ void unpack2(u64 v, float& lo, float& hi){
    asm("mov.b64 {%0,%1}, %2;" : "=f"(lo), "=f"(hi) : "l"(v));
}
__device__ __forceinline__ u64 ffma2(u64 a, u64 b, u64 c){
    u64 d; asm("fma.rn.f32x2 %0, %1, %2, %3;" : "=l"(d) : "l"(a), "l"(b), "l"(c)); return d;
}
__device__ __forceinline__ u64 fadd2(u64 a, u64 b){
    u64 d; asm("add.rn.f32x2 %0, %1, %2;" : "=l"(d) : "l"(a), "l"(b)); return d;
}
// tanh = 1 - 2/(exp(2x)+1) via ex2.approx + rcp.approx (~1e-7 rel err)
__device__ __forceinline__ float fast_tanh(float x){
    float e; asm("ex2.approx.f32 %0, %1;" : "=f"(e) : "f"(x * 2.88539008177792681f));
    float r; asm("rcp.approx.f32 %0, %1;" : "=f"(r) : "f"(e + 1.0f));
    return fmaf(-2.0f, r, 1.0f);
}

struct __align__(16) Smem {
    float xsraw[NELEM];       // raw env scalar x per (pair,element)
    float xsw[NELEM];         // x * symmetry_weight * scale (0 on padded slots)
    float h1s[64][24];
    float h2s[64][48];
    float rrs[96][4];
    float red[2][4][48];      // [channel-half][quarter][m2]
};

__global__ __launch_bounds__(192, 2)
void descrpt_se_t_main(const int*   __restrict__ nlist,
                       const float* __restrict__ coord,
                       const int*   __restrict__ atype,
                       const float* __restrict__ meanv,
                       const float* __restrict__ stdv,
                       const float* __restrict__ W1, const float* __restrict__ b1,
                       const float* __restrict__ W2, const float* __restrict__ b2,
                       const float* __restrict__ W3, const float* __restrict__ b3)
{
    extern __shared__ __align__(16) char smraw[];
    Smem* sm = (Smem*)smraw;

    const int bid  = blockIdx.x;
    const int i    = bid >> 2;      // atom
    const int part = bid & 3;       // tile-stride slice
    const int tid  = threadIdx.x;

    // ---- env rows (only diff components 1..3 are used downstream) ----
    if (tid < NNEI){
        int n  = tid;
        int nl = nlist[i*NNEI + n];
        bool mask = nl >= 0;
        int idx = mask ? nl : 0;
        float dx = coord[idx*3+0] - coord[i*3+0];
        float dy = coord[idx*3+1] - coord[i*3+1];
        float dz = coord[idx*3+2] - coord[i*3+2];
        float d2  = dx*dx + dy*dy + dz*dz;
        float len = sqrtf(d2) + (mask ? 0.f : 1.f);
        float inv2 = 1.f / (len*len);
        float sw;
        if (len <= 0.5f)      sw = 1.f;
        else if (len >= 6.f)  sw = 0.f;
        else {
            float uu = (len - 0.5f) * (1.f/5.5f);
            float pp = fmaf(fmaf(-6.f, uu, 15.f), uu, -10.f);
            sw = fmaf(uu*uu*uu, pp, 1.f);
        }
        if (!mask) sw = 0.f;
        int t  = atype[i];
        int mb = (t*NNEI + n)*4;
        sm->rrs[n][0] = (dx*inv2*sw - meanv[mb+1]) / stdv[mb+1];
        sm->rrs[n][1] = (dy*inv2*sw - meanv[mb+2]) / stdv[mb+2];
        sm->rrs[n][2] = (dz*inv2*sw - meanv[mb+3]) / stdv[mb+3];
        sm->rrs[n][3] = 0.f;
    }
    // zero xs (covers padded slots)
    for (int e = tid; e < NELEM; e += 192){ sm->xsraw[e] = 0.f; sm->xsw[e] = 0.f; }
    __syncthreads();

    // ---- precompute ALL env scalars once (kills the per-tile serial search) ----
    // pair 1 (0,1): dense 32x64 at base 576, scale 1/2048
    for (int el = tid; el < 2048; el += 192){
        int j = el >> 6, k = el & 63;
        float4 a = *(const float4*)sm->rrs[j];
        float4 b = *(const float4*)sm->rrs[32 + k];
        float x = a.x*b.x + a.y*b.y + a.z*b.z;
        sm->xsraw[576 + el] = x;
        sm->xsw[576 + el]   = x * (1.f/2048.f);
    }
    // triangular pairs: p0 (n=32, base 0, 1/1024), p2 (n=64, base 2624, 1/4096)
    if (tid < 96){
        int row = tid;
        int j, n, base; float sc; int roff;
        if (row < 32){ j = row;      n = 32; base = 0;    sc = 1.f/1024.f; }
        else         { j = row - 32; n = 64; base = 2624; sc = 1.f/4096.f; }
        roff = (row < 32) ? 0 : 32;
        int off = base + j*n - (j*(j-1))/2 - j;   // entry for k sits at off + k
        float4 a = *(const float4*)sm->rrs[roff + j];
        for (int k = j; k < n; ++k){
            float4 b = *(const float4*)sm->rrs[roff + k];
            float x = a.x*b.x + a.y*b.y + a.z*b.z;
            sm->xsraw[off + k] = x;
            sm->xsw[off + k]   = x * sc * ((k == j) ? 1.f : 2.f);
        }
    }
    __syncthreads();

    // thread roles
    const int cA      = tid % 24;   // phase-A channel
    const int eA0     = tid / 24;   // phase-A element base (0..7)
    const int m2      = tid % 48;   // phase-B channel / phase-C channel pair (m2, m2+48)
    const int esub    = tid / 48;   // phase-B element offset (0..3)
    const int quarter = tid / 48;   // phase-C element offset (0..3)
    const int cskip   = (m2 >= 24) ? m2 - 24 : m2;

    float tot0 = 0.f, tot1 = 0.f;

    #pragma unroll 1
    for (int p = 0; p < 3; ++p){
        int ntl, pb;
        if (p == 0)      { ntl = 9;  pb = 0;    }
        else if (p == 1) { ntl = 32; pb = 576;  }
        else             { ntl = 33; pb = 2624; }

        // per-pair weights -> registers (packed over K for f32x2)
        u64 w2p[12], w3a[24], w3b[24];
        const float* W2p = W2 + p*24*48;
        const float* W3p = W3 + p*48*96;
        #pragma unroll
        for (int q = 0; q < 12; ++q)
            w2p[q] = pack2(W2p[(2*q)*48 + m2], W2p[(2*q+1)*48 + m2]);
        #pragma unroll
        for (int q = 0; q < 24; ++q){
            w3a[q] = pack2(W3p[(2*q)*96 + m2],      W3p[(2*q+1)*96 + m2]);
            w3b[q] = pack2(W3p[(2*q)*96 + m2 + 48], W3p[(2*q+1)*96 + m2 + 48]);
        }
        const float b2r  = b2[p*48 + m2];
        const float b3r0 = b3[p*96 + m2];
        const float b3r1 = b3[p*96 + m2 + 48];
        const float w1c  = W1[p*24 + cA];
        const float b1c  = b1[p*24 + cA];

        // ---- software-pipelined tiles: [A(t+1) || C(t)] share a barrier region ----
        int t = part;                 // every part has >=2 tiles for every pair (ntl>=9)
        {   // A(first)
            const int e0 = pb + (t << 6);
            #pragma unroll
            for (int it = 0; it < 8; ++it){
                int e = eA0 + 8*it;
                float x = sm->xsraw[e0 + e];
                sm->h1s[e][cA] = fast_tanh(fmaf(x, w1c, b1c));
            }
        }
        __syncthreads();

        #pragma unroll 1
        for (;;){
            // ---- phase B: h2 = tanh(h1@W2 + b2) + h1[c%24] ----
            #pragma unroll 2
            for (int it = 0; it < 16; ++it){
                int e = 4*it + esub;
                const ulonglong2* row = (const ulonglong2*)sm->h1s[e];
                u64 accA = pack2(b2r, 0.f);
                u64 accB = 0ULL;
                #pragma unroll
                for (int q = 0; q < 6; ++q){
                    ulonglong2 v = row[q];
                    accA = ffma2(v.x, w2p[2*q],   accA);
                    accB = ffma2(v.y, w2p[2*q+1], accB);
                }
                float lo, hi; unpack2(fadd2(accA, accB), lo, hi);
                sm->h2s[e][m2] = fast_tanh(lo + hi) + sm->h1s[e][cskip];
            }
            __syncthreads();

            const int e0c = pb + (t << 6);
            const int tn  = t + 4;

            // ---- phase A for next tile (overlaps with C in this region) ----
            if (tn < ntl){
                const int e0n = pb + (tn << 6);
                #pragma unroll
                for (int it = 0; it < 8; ++it){
                    int e = eA0 + 8*it;
                    float x = sm->xsraw[e0n + e];
                    sm->h1s[e][cA] = fast_tanh(fmaf(x, w1c, b1c));
                }
            }

            // ---- phase C: two channels per thread, h2 row shared across both ----
            #pragma unroll 2
            for (int itc = 0; itc < 16; ++itc){
                int e = 4*itc + quarter;
                const ulonglong2* row = (const ulonglong2*)sm->h2s[e];
                u64 a0A = pack2(b3r0, 0.f), a0B = 0ULL;
                u64 a1A = pack2(b3r1, 0.f), a1B = 0ULL;
                #pragma unroll
                for (int q = 0; q < 12; ++q){
                    ulonglong2 v = row[q];
                    a0A = ffma2(v.x, w3a[2*q],   a0A);
                    a0B = ffma2(v.y, w3a[2*q+1], a0B);
                    a1A = ffma2(v.x, w3b[2*q],   a1A);
                    a1B = ffma2(v.y, w3b[2*q+1], a1B);
                }
                float xw   = sm->xsw[e0c + e];
                float skip = sm->h2s[e][m2];
                float l0, h0; unpack2(fadd2(a0A, a0B), l0, h0);
                float l1, h1; unpack2(fadd2(a1A, a1B), l1, h1);
                float g0 = fast_tanh(l0 + h0) + skip;
                float g1 = fast_tanh(l1 + h1) + skip;
                tot0 = fmaf(xw, g0, tot0);
                tot1 = fmaf(xw, g1, tot1);
            }
            __syncthreads();

            if (tn >= ntl) break;
            t = tn;
        }
    }

    // ---- combine the 4 element-quarters, write this part's slice ----
    sm->red[0][quarter][m2] = tot0;
    sm->red[1][quarter][m2] = tot1;
    __syncthreads();
    if (tid < 96){
        int c = tid / 48, mm = tid % 48;
        float s = sm->red[c][0][mm] + sm->red[c][1][mm]
                + sm->red[c][2][mm] + sm->red[c][3][mm];
        g_part[part*NOUT + i*NG + c*48 + mm] = s;
    }
}

__global__ void descrpt_reduce(float* __restrict__ out)
{
    int idx = blockIdx.x * 256 + threadIdx.x;   // 96*256 = 24576 = NOUT
    out[idx] = g_part[idx]
             + g_part[idx + NOUT]
             + g_part[idx + 2*NOUT]
             + g_part[idx + 3*NOUT];
}

extern "C" void kernel_launch(void* const* d_in, const int* in_sizes, int n_in,
                              void* d_out, int out_size)
{
    const int*   nlist = (const int*)  d_in[0];
    const float* coord = (const float*)d_in[1];
    const int*   atype = (const int*)  d_in[2];
    const float* meanv = (const float*)d_in[3];
    const float* stdv  = (const float*)d_in[4];
    const float* W1    = (const float*)d_in[5];
    const float* b1    = (const float*)d_in[6];
    const float* W2    = (const float*)d_in[7];
    const float* b2    = (const float*)d_in[8];
    const float* W3    = (const float*)d_in[9];
    const float* b3    = (const float*)d_in[10];

    cudaFuncSetAttribute(descrpt_se_t_main,
                         cudaFuncAttributeMaxDynamicSharedMemorySize,
                         (int)sizeof(Smem));

    descrpt_se_t_main<<<NLOC * NPART, 192, sizeof(Smem)>>>(
        nlist, coord, atype, meanv, stdv, W1, b1, W2, b2, W3, b3);
    descrpt_reduce<<<NG, 256>>>((float*)d_out);
}